// round 6
// baseline (speedup 1.0000x reference)
#include <cuda_runtime.h>

#define NN 50000
#define NE 800000
#define H  64
#define REL 5
#define NB 196          // (NN + 255) / 256

// ---- device scratch (static globals; no runtime allocation) ----
__device__ float g_z[NN * H];            // x * dis[col]  (12.8 MB)
__device__ float g_y[REL * NN * H];      // y_r = x @ W_rel[r]  (64 MB)
__device__ float g_m[NN * H];            // fused message (edge-pass output)
__device__ int   g_deg[NN];              // col-degree (for gcn norm)
__device__ int   g_cnt[NN];              // row-degree (for sort)
__device__ int   g_off[NN + 1];          // CSR offsets by dst
__device__ int   g_cur[NN];              // scatter cursors
__device__ int   g_es[NE];               // sorted packed edges: src | type<<16
__device__ int   g_bsum[NB];             // per-block sums for scan
__device__ int   g_boff[NB];             // scanned block offsets
__device__ float g_WC[6 * H * H];        // [W_in | W_in@W_rel_r]
__device__ float g_BC[6 * H];            // [b    | b@W_rel_r]

__global__ void k_zero() {
    int i = blockIdx.x * blockDim.x + threadIdx.x;
    int stride = gridDim.x * blockDim.x;
    for (int j = i; j < NN; j += stride) { g_deg[j] = 0; g_cnt[j] = 0; }
}

// Combined weights: WC[0]=W_in, BC[0]=b_in; WC[1+r]=W_in@W_rel[r], BC[1+r]=b@W_rel[r]
__global__ void k_wcomb(const float* __restrict__ Win, const float* __restrict__ bin,
                        const float* __restrict__ Wrel) {
    int idx = blockIdx.x * blockDim.x + threadIdx.x;
    if (idx >= 6 * H * H) return;
    int m = idx >> 12, k = (idx >> 6) & 63, h = idx & 63;
    if (m == 0) {
        g_WC[idx] = Win[k * H + h];
        if (k == 0) g_BC[h] = bin[h];
    } else {
        const float* Wr = Wrel + (m - 1) * H * H;
        float s = 0.f;
        #pragma unroll 8
        for (int j = 0; j < H; j++) s += Win[k * H + j] * Wr[j * H + h];
        g_WC[idx] = s;
        if (k == 0) {
            float sb = 0.f;
            for (int j = 0; j < H; j++) sb += bin[j] * Wr[j * H + h];
            g_BC[m * H + h] = sb;
        }
    }
}

__global__ void k_deg(const int* __restrict__ ei) {
    int e = blockIdx.x * blockDim.x + threadIdx.x;
    if (e < NE) {
        atomicAdd(&g_deg[ei[NE + e]], 1);   // col-degree (norm)
        atomicAdd(&g_cnt[ei[e]], 1);        // row-degree (sort)
    }
}

// ---- 3-phase parallel exclusive scan of g_cnt -> g_off/g_cur ----
__global__ void __launch_bounds__(256) k_bsum() {
    __shared__ int s[256];
    int t = threadIdx.x;
    int idx = blockIdx.x * 256 + t;
    int v = idx < NN ? g_cnt[idx] : 0;
    s[t] = v;
    __syncthreads();
    for (int d = 128; d > 0; d >>= 1) {
        if (t < d) s[t] += s[t + d];
        __syncthreads();
    }
    if (t == 0) g_bsum[blockIdx.x] = s[0];
}

__global__ void __launch_bounds__(256) k_scanb() {
    __shared__ int s[256];
    int t = threadIdx.x;
    int v = t < NB ? g_bsum[t] : 0;
    s[t] = v;
    __syncthreads();
    #pragma unroll
    for (int d = 1; d < 256; d <<= 1) {
        int u = (t >= d) ? s[t - d] : 0;
        __syncthreads();
        s[t] += u;
        __syncthreads();
    }
    if (t < NB) g_boff[t] = s[t] - v;   // exclusive
}

__global__ void __launch_bounds__(256) k_off() {
    __shared__ int s[256];
    int t = threadIdx.x;
    int idx = blockIdx.x * 256 + t;
    int v = idx < NN ? g_cnt[idx] : 0;
    s[t] = v;
    __syncthreads();
    #pragma unroll
    for (int d = 1; d < 256; d <<= 1) {
        int u = (t >= d) ? s[t - d] : 0;
        __syncthreads();
        s[t] += u;
        __syncthreads();
    }
    int excl = s[t] - v + g_boff[blockIdx.x];
    if (idx < NN) { g_off[idx] = excl; g_cur[idx] = excl; }
    if (idx == NN - 1) g_off[NN] = NE;
}

__global__ void k_scatter(const int* __restrict__ ei, const int* __restrict__ et) {
    int e = blockIdx.x * blockDim.x + threadIdx.x;
    if (e >= NE) return;
    int r = ei[e], c = ei[NE + e], tp = et[e];
    int pos = atomicAdd(&g_cur[r], 1);
    g_es[pos] = c | (tp << 16);
}

#define SA_STRIDE 68   // floats; multiple of 4 (16B alignment), 68 mod 32 = 4 banks

// Node GEMM: 64x64 tile, 4x4 micro-tile, 3 weight matrices fused per pass.
// Dynamic smem: 3 * 64*64 floats (48KB) + 17.4KB static (opt-in required).
__global__ void __launch_bounds__(256) k_node(const float* __restrict__ risk) {
    extern __shared__ float sW[];                 // 3 * 4096 floats
    __shared__ float sAT[H * SA_STRIDE];
    __shared__ float sB[3 * H];
    int t = threadIdx.x;
    int node0 = blockIdx.x * 64;

    for (int i = t; i < 64 * 16; i += 256) {
        int nd = i >> 4, kg = i & 15;
        float4 a = make_float4(0.f, 0.f, 0.f, 0.f);
        if (node0 + nd < NN) a = ((const float4*)risk)[(node0 + nd) * 16 + kg];
        sAT[(kg * 4 + 0) * SA_STRIDE + nd] = a.x;
        sAT[(kg * 4 + 1) * SA_STRIDE + nd] = a.y;
        sAT[(kg * 4 + 2) * SA_STRIDE + nd] = a.z;
        sAT[(kg * 4 + 3) * SA_STRIDE + nd] = a.w;
    }

    int rg = t >> 4;   // 16 node groups x 4 nodes
    int cg = t & 15;   // 16 col groups  x 4 cols

    for (int p = 0; p < 2; p++) {
        __syncthreads();
        #pragma unroll
        for (int i = 0; i < 12; i++)
            ((float4*)sW)[t + 256 * i] = ((const float4*)(g_WC + 3 * p * H * H))[t + 256 * i];
        if (t < 192) sB[t] = g_BC[3 * p * H + t];
        __syncthreads();

        float4 acc[3][4];
        #pragma unroll
        for (int q = 0; q < 3; q++) {
            float4 b = ((float4*)sB)[q * 16 + cg];
            #pragma unroll
            for (int j = 0; j < 4; j++) acc[q][j] = b;
        }

        #pragma unroll 8
        for (int k = 0; k < H; k++) {
            float4 av = *(const float4*)&sAT[k * SA_STRIDE + rg * 4];
            #pragma unroll
            for (int q = 0; q < 3; q++) {
                float4 w = ((const float4*)sW)[q * 1024 + k * 16 + cg];
                acc[q][0].x += av.x * w.x; acc[q][0].y += av.x * w.y; acc[q][0].z += av.x * w.z; acc[q][0].w += av.x * w.w;
                acc[q][1].x += av.y * w.x; acc[q][1].y += av.y * w.y; acc[q][1].z += av.y * w.z; acc[q][1].w += av.y * w.w;
                acc[q][2].x += av.z * w.x; acc[q][2].y += av.z * w.y; acc[q][2].z += av.z * w.z; acc[q][2].w += av.z * w.w;
                acc[q][3].x += av.w * w.x; acc[q][3].y += av.w * w.y; acc[q][3].z += av.w * w.z; acc[q][3].w += av.w * w.w;
            }
        }

        int nbase = node0 + rg * 4;
        #pragma unroll
        for (int q = 0; q < 3; q++) {
            int m = 3 * p + q;
            #pragma unroll
            for (int j = 0; j < 4; j++) {
                int n = nbase + j;
                if (n >= NN) continue;
                if (m == 0) {
                    int dg = g_deg[n];
                    float dis = dg > 0 ? rsqrtf((float)dg) : 0.f;
                    float4 zz = make_float4(acc[q][j].x * dis, acc[q][j].y * dis,
                                            acc[q][j].z * dis, acc[q][j].w * dis);
                    ((float4*)g_z)[n * 16 + cg] = zz;
                } else {
                    ((float4*)g_y)[((m - 1) * NN + n) * 16 + cg] = acc[q][j];
                }
            }
        }
    }
}

// Sorted edge pass: one warp per dst node, float2 per lane.
// Unrolled by 2 edges (independent chains) for MLP.
__global__ void __launch_bounds__(256) k_edge2() {
    int t = threadIdx.x;
    int node = blockIdx.x * 8 + (t >> 5);
    if (node >= NN) return;
    int l = t & 31;
    int beg = g_off[node], end = g_off[node + 1];

    float2 gcn0 = make_float2(0.f, 0.f), gcn1 = make_float2(0.f, 0.f);
    float2 ss0  = make_float2(0.f, 0.f), ss1  = make_float2(0.f, 0.f);
    float2 nm0  = make_float2(0.f, 0.f), nm1  = make_float2(0.f, 0.f);

    int i = beg;
    for (; i + 1 < end; i += 2) {
        int pka = __ldg(&g_es[i]);
        int pkb = __ldg(&g_es[i + 1]);
        int ca = pka & 0xFFFF, ta = pka >> 16;
        int cb = pkb & 0xFFFF, tb = pkb >> 16;
        float2 za = __ldg(&((const float2*)g_z)[ca * 32 + l]);
        float2 ya = __ldg(&((const float2*)g_y)[(ta * NN + ca) * 32 + l]);
        float2 zb = __ldg(&((const float2*)g_z)[cb * 32 + l]);
        float2 yb = __ldg(&((const float2*)g_y)[(tb * NN + cb) * 32 + l]);
        float exa = __expf(ya.x), eya = __expf(ya.y);
        float exb = __expf(yb.x), eyb = __expf(yb.y);
        gcn0.x += za.x;        gcn0.y += za.y;
        ss0.x  += exa;         ss0.y  += eya;
        nm0.x  += ya.x * exa;  nm0.y  += ya.y * eya;
        gcn1.x += zb.x;        gcn1.y += zb.y;
        ss1.x  += exb;         ss1.y  += eyb;
        nm1.x  += yb.x * exb;  nm1.y  += yb.y * eyb;
    }
    if (i < end) {
        int pk = __ldg(&g_es[i]);
        int c = pk & 0xFFFF, tp = pk >> 16;
        float2 zv = __ldg(&((const float2*)g_z)[c * 32 + l]);
        float2 yv = __ldg(&((const float2*)g_y)[(tp * NN + c) * 32 + l]);
        float ex = __expf(yv.x), ey = __expf(yv.y);
        gcn0.x += zv.x;       gcn0.y += zv.y;
        ss0.x  += ex;         ss0.y  += ey;
        nm0.x  += yv.x * ex;  nm0.y  += yv.y * ey;
    }

    float2 gcn = make_float2(gcn0.x + gcn1.x, gcn0.y + gcn1.y);
    float2 ss  = make_float2(ss0.x + ss1.x,  ss0.y + ss1.y);
    float2 nm  = make_float2(nm0.x + nm1.x,  nm0.y + nm1.y);

    int dg = g_deg[node];
    float dis = dg > 0 ? rsqrtf((float)dg) : 0.f;
    float2 m;
    m.x = dis * gcn.x + 0.5f * fmaxf(nm.x / (ss.x + 1e-16f), 0.f);
    m.y = dis * gcn.y + 0.5f * fmaxf(nm.y / (ss.y + 1e-16f), 0.f);
    ((float2*)g_m)[node * 32 + l] = m;
}

// Output GEMM: out = m @ W_out + b_out. 64x64 tile, 4x4 micro.
__global__ void __launch_bounds__(256) k_out(const float* __restrict__ Wout,
                                             const float* __restrict__ bout,
                                             float* __restrict__ out) {
    __shared__ float sMT[H * SA_STRIDE];
    __shared__ float sWo[H * H];
    __shared__ float sB[H];
    int t = threadIdx.x;
    int node0 = blockIdx.x * 64;

    for (int i = t; i < 64 * 16; i += 256) {
        int nd = i >> 4, kg = i & 15;
        float4 mm = make_float4(0.f, 0.f, 0.f, 0.f);
        if (node0 + nd < NN) mm = ((const float4*)g_m)[(node0 + nd) * 16 + kg];
        sMT[(kg * 4 + 0) * SA_STRIDE + nd] = mm.x;
        sMT[(kg * 4 + 1) * SA_STRIDE + nd] = mm.y;
        sMT[(kg * 4 + 2) * SA_STRIDE + nd] = mm.z;
        sMT[(kg * 4 + 3) * SA_STRIDE + nd] = mm.w;
    }

    #pragma unroll
    for (int i = 0; i < 4; i++)
        ((float4*)sWo)[t + 256 * i] = ((const float4*)Wout)[t + 256 * i];
    if (t < H) sB[t] = bout[t];
    __syncthreads();

    int rg = t >> 4, cg = t & 15;
    float4 b = ((float4*)sB)[cg];
    float4 acc[4];
    #pragma unroll
    for (int j = 0; j < 4; j++) acc[j] = b;

    #pragma unroll 16
    for (int k = 0; k < H; k++) {
        float4 av = *(const float4*)&sMT[k * SA_STRIDE + rg * 4];
        float4 w  = ((const float4*)sWo)[k * 16 + cg];
        acc[0].x += av.x * w.x; acc[0].y += av.x * w.y; acc[0].z += av.x * w.z; acc[0].w += av.x * w.w;
        acc[1].x += av.y * w.x; acc[1].y += av.y * w.y; acc[1].z += av.y * w.z; acc[1].w += av.y * w.w;
        acc[2].x += av.z * w.x; acc[2].y += av.z * w.y; acc[2].z += av.z * w.z; acc[2].w += av.z * w.w;
        acc[3].x += av.w * w.x; acc[3].y += av.w * w.y; acc[3].z += av.w * w.z; acc[3].w += av.w * w.w;
    }

    int nbase = node0 + rg * 4;
    #pragma unroll
    for (int j = 0; j < 4; j++) {
        int n = nbase + j;
        if (n < NN) ((float4*)out)[n * 16 + cg] = acc[j];
    }
}

extern "C" void kernel_launch(void* const* d_in, const int* in_sizes, int n_in,
                              void* d_out, int out_size) {
    const float* risk = (const float*)d_in[0];
    // d_in[1] = edge_weight (unused by the reference)
    const float* Win  = (const float*)d_in[2];
    const float* bin  = (const float*)d_in[3];
    const float* Wrel = (const float*)d_in[4];
    const float* Wout = (const float*)d_in[5];
    const float* bout = (const float*)d_in[6];
    const int*   ei   = (const int*)d_in[7];   // [2, NE]: row (dst), col (src)
    const int*   et   = (const int*)d_in[8];
    float* out = (float*)d_out;

    // Opt in to >48KB dynamic smem for the fused node GEMM (idempotent, not a
    // stream op, no allocation — graph-capture safe).
    cudaFuncSetAttribute(k_node, cudaFuncAttributeMaxDynamicSharedMemorySize,
                         3 * H * H * (int)sizeof(float));

    k_zero<<<128, 256>>>();
    k_wcomb<<<(6 * H * H + 255) / 256, 256>>>(Win, bin, Wrel);
    k_deg<<<(NE + 255) / 256, 256>>>(ei);
    k_bsum<<<NB, 256>>>();
    k_scanb<<<1, 256>>>();
    k_off<<<NB, 256>>>();
    k_scatter<<<(NE + 255) / 256, 256>>>(ei, et);
    k_node<<<(NN + 63) / 64, 256, 3 * H * H * sizeof(float)>>>(risk);
    k_edge2<<<(NN + 7) / 8, 256>>>();
    k_out<<<(NN + 63) / 64, 256>>>(Wout, bout, out);
}

// round 8
// speedup vs baseline: 1.0646x; 1.0646x over previous
#include <cuda_runtime.h>
#include <cuda_bf16.h>
#include <mma.h>
#include <cstdint>

using namespace nvcuda;

#define NN 50000
#define NE 800000
#define H  64
#define REL 5
#define NB 196          // (NN + 255) / 256

// ---- device scratch (static globals; no runtime allocation) ----
__device__ float g_z[NN * H];            // x * dis[col]  (12.8 MB)
__device__ float g_y[REL * NN * H];      // y_r = x @ W_rel[r]  (64 MB)
__device__ float g_m[NN * H];            // fused message (edge-pass output)
__device__ int   g_deg[NN];              // col-degree (for gcn norm)
__device__ int   g_cnt[NN];              // row-degree (for sort)
__device__ int   g_off[NN + 1];          // CSR offsets by dst
__device__ int   g_cur[NN];              // scatter cursors
__device__ int   g_es[NE];               // sorted packed edges: src | type<<16
__device__ int   g_bsum[NB];             // per-block sums for scan
__device__ int   g_boff[NB];             // scanned block offsets
__device__ float g_WC[6 * H * H];        // [W_in | W_in@W_rel_r]
__device__ float g_BC[6 * H];            // [b    | b@W_rel_r]

// ================= setup kernels =================
__global__ void k_zero() {
    int i = blockIdx.x * blockDim.x + threadIdx.x;
    int stride = gridDim.x * blockDim.x;
    for (int j = i; j < NN; j += stride) { g_deg[j] = 0; g_cnt[j] = 0; }
}

// Combined weights: WC[0]=W_in, BC[0]=b_in; WC[1+r]=W_in@W_rel[r], BC[1+r]=b@W_rel[r]
__global__ void k_wcomb(const float* __restrict__ Win, const float* __restrict__ bin,
                        const float* __restrict__ Wrel) {
    int idx = blockIdx.x * blockDim.x + threadIdx.x;
    if (idx >= 6 * H * H) return;
    int m = idx >> 12, k = (idx >> 6) & 63, h = idx & 63;
    if (m == 0) {
        g_WC[idx] = Win[k * H + h];
        if (k == 0) g_BC[h] = bin[h];
    } else {
        const float* Wr = Wrel + (m - 1) * H * H;
        float s = 0.f;
        #pragma unroll 8
        for (int j = 0; j < H; j++) s += Win[k * H + j] * Wr[j * H + h];
        g_WC[idx] = s;
        if (k == 0) {
            float sb = 0.f;
            for (int j = 0; j < H; j++) sb += bin[j] * Wr[j * H + h];
            g_BC[m * H + h] = sb;
        }
    }
}

__global__ void k_deg(const int* __restrict__ ei) {
    int e = blockIdx.x * blockDim.x + threadIdx.x;
    if (e < NE) {
        atomicAdd(&g_deg[ei[NE + e]], 1);   // col-degree (norm)
        atomicAdd(&g_cnt[ei[e]], 1);        // row-degree (sort)
    }
}

// ---- 3-phase parallel exclusive scan of g_cnt -> g_off/g_cur ----
__global__ void __launch_bounds__(256) k_bsum() {
    __shared__ int s[256];
    int t = threadIdx.x;
    int idx = blockIdx.x * 256 + t;
    int v = idx < NN ? g_cnt[idx] : 0;
    s[t] = v;
    __syncthreads();
    for (int d = 128; d > 0; d >>= 1) {
        if (t < d) s[t] += s[t + d];
        __syncthreads();
    }
    if (t == 0) g_bsum[blockIdx.x] = s[0];
}

__global__ void __launch_bounds__(256) k_scanb() {
    __shared__ int s[256];
    int t = threadIdx.x;
    int v = t < NB ? g_bsum[t] : 0;
    s[t] = v;
    __syncthreads();
    #pragma unroll
    for (int d = 1; d < 256; d <<= 1) {
        int u = (t >= d) ? s[t - d] : 0;
        __syncthreads();
        s[t] += u;
        __syncthreads();
    }
    if (t < NB) g_boff[t] = s[t] - v;   // exclusive
}

__global__ void __launch_bounds__(256) k_off() {
    __shared__ int s[256];
    int t = threadIdx.x;
    int idx = blockIdx.x * 256 + t;
    int v = idx < NN ? g_cnt[idx] : 0;
    s[t] = v;
    __syncthreads();
    #pragma unroll
    for (int d = 1; d < 256; d <<= 1) {
        int u = (t >= d) ? s[t - d] : 0;
        __syncthreads();
        s[t] += u;
        __syncthreads();
    }
    int excl = s[t] - v + g_boff[blockIdx.x];
    if (idx < NN) { g_off[idx] = excl; g_cur[idx] = excl; }
    if (idx == NN - 1) g_off[NN] = NE;
}

__global__ void k_scatter(const int* __restrict__ ei, const int* __restrict__ et) {
    int e = blockIdx.x * blockDim.x + threadIdx.x;
    if (e >= NE) return;
    int r = ei[e], c = ei[NE + e], tp = et[e];
    int pos = atomicAdd(&g_cur[r], 1);
    g_es[pos] = c | (tp << 16);
}

// ================= tensor-core node GEMM (wmma bf16 split-3) =================
// Per CTA: 128 nodes, 8 warps; warp w owns rows [w*16, w*16+16).
// D = Ah@Bh + Al@Bh + Ah@Bl  (bf16 hi/lo split, fp32 accumulate).
// Dynamic smem (88KB, opt-in): Ah 128x72 bf16 | Al | Wh 64x72 | Wl | staging 128x68 f32.
#define LDAB 72      // bf16 leading dim (mult of 8 elems = 16B)
#define LDST 68      // float leading dim for staging (mult of 4 elems = 16B)
#define TCN_SMEM (2 * 128 * LDAB * 2 + 2 * 64 * LDAB * 2 + 128 * LDST * 4)

__global__ void __launch_bounds__(256) k_node_tc(const float* __restrict__ risk) {
    extern __shared__ char smc[];
    __nv_bfloat16* sAh = (__nv_bfloat16*)smc;
    __nv_bfloat16* sAl = sAh + 128 * LDAB;
    __nv_bfloat16* sWh = sAl + 128 * LDAB;
    __nv_bfloat16* sWl = sWh + 64 * LDAB;
    float*         sSt = (float*)(sWl + 64 * LDAB);

    int t = threadIdx.x;
    int w = t >> 5, lane = t & 31;
    int node0 = blockIdx.x * 128;

    // load + bf16-split A (128 x 64)
    for (int i = t; i < 128 * 64; i += 256) {
        int r = i >> 6, c = i & 63;
        float v = 0.f;
        int n = node0 + r;
        if (n < NN) v = __ldg(&risk[n * 64 + c]);
        __nv_bfloat16 hi = __float2bfloat16(v);
        sAh[r * LDAB + c] = hi;
        sAl[r * LDAB + c] = __float2bfloat16(v - __bfloat162float(hi));
    }

    for (int m = 0; m < 6; m++) {
        __syncthreads();   // previous iteration's reads of sW done
        for (int i = t; i < 64 * 64; i += 256) {
            int k = i >> 6, o = i & 63;
            float v = g_WC[m * 4096 + i];
            __nv_bfloat16 hi = __float2bfloat16(v);
            sWh[k * LDAB + o] = hi;
            sWl[k * LDAB + o] = __float2bfloat16(v - __bfloat162float(hi));
        }
        __syncthreads();

        wmma::fragment<wmma::accumulator, 16, 16, 16, float> acc[4];
        #pragma unroll
        for (int n = 0; n < 4; n++) wmma::fill_fragment(acc[n], 0.f);

        #pragma unroll
        for (int k = 0; k < 4; k++) {
            wmma::fragment<wmma::matrix_a, 16, 16, 16, __nv_bfloat16, wmma::row_major> ah, al;
            wmma::load_matrix_sync(ah, &sAh[(w * 16) * LDAB + k * 16], LDAB);
            wmma::load_matrix_sync(al, &sAl[(w * 16) * LDAB + k * 16], LDAB);
            #pragma unroll
            for (int n = 0; n < 4; n++) {
                wmma::fragment<wmma::matrix_b, 16, 16, 16, __nv_bfloat16, wmma::row_major> bh, bl;
                wmma::load_matrix_sync(bh, &sWh[(k * 16) * LDAB + n * 16], LDAB);
                wmma::load_matrix_sync(bl, &sWl[(k * 16) * LDAB + n * 16], LDAB);
                wmma::mma_sync(acc[n], ah, bh, acc[n]);
                wmma::mma_sync(acc[n], al, bh, acc[n]);
                wmma::mma_sync(acc[n], ah, bl, acc[n]);
            }
        }

        // per-warp staging + epilogue (staging region is warp-private)
        float* st = sSt + (w * 16) * LDST;
        #pragma unroll
        for (int n = 0; n < 4; n++)
            wmma::store_matrix_sync(st + n * 16, acc[n], LDST, wmma::mem_row_major);
        __syncwarp();

        for (int i = lane; i < 16 * 16; i += 32) {
            int rr = i >> 4, cgp = i & 15;
            int n = node0 + w * 16 + rr;
            if (n >= NN) continue;
            float4 v = *(float4*)&st[rr * LDST + cgp * 4];
            float4 b = ((const float4*)&g_BC[m * 64])[cgp];
            v.x += b.x; v.y += b.y; v.z += b.z; v.w += b.w;
            if (m == 0) {
                int dg = g_deg[n];
                float dis = dg > 0 ? rsqrtf((float)dg) : 0.f;
                v.x *= dis; v.y *= dis; v.z *= dis; v.w *= dis;
                ((float4*)g_z)[n * 16 + cgp] = v;
            } else {
                ((float4*)g_y)[((m - 1) * NN + n) * 16 + cgp] = v;
            }
        }
    }
}

// ================= sorted edge pass =================
// One warp per dst node, float2 per lane. Register accumulation, fused epilogue.
__global__ void __launch_bounds__(256) k_edge2() {
    int t = threadIdx.x;
    int node = blockIdx.x * 8 + (t >> 5);
    if (node >= NN) return;
    int l = t & 31;
    int beg = g_off[node], end = g_off[node + 1];

    float2 gcn = make_float2(0.f, 0.f);
    float2 ss  = make_float2(0.f, 0.f);
    float2 nm  = make_float2(0.f, 0.f);

    #pragma unroll 2
    for (int i = beg; i < end; i++) {
        int pk = __ldg(&g_es[i]);
        int c  = pk & 0xFFFF;
        int tp = pk >> 16;
        float2 zv = __ldg(&((const float2*)g_z)[c * 32 + l]);
        float2 yv = __ldg(&((const float2*)g_y)[(tp * NN + c) * 32 + l]);
        float ex = __expf(yv.x), ey = __expf(yv.y);
        gcn.x += zv.x;       gcn.y += zv.y;
        ss.x  += ex;         ss.y  += ey;
        nm.x  += yv.x * ex;  nm.y  += yv.y * ey;
    }

    int dg = g_deg[node];
    float dis = dg > 0 ? rsqrtf((float)dg) : 0.f;
    float2 m;
    m.x = dis * gcn.x + 0.5f * fmaxf(nm.x / (ss.x + 1e-16f), 0.f);
    m.y = dis * gcn.y + 0.5f * fmaxf(nm.y / (ss.y + 1e-16f), 0.f);
    ((float2*)g_m)[node * 32 + l] = m;
}

// ================= output GEMM =================
#define SA_STRIDE 68
__global__ void __launch_bounds__(256) k_out(const float* __restrict__ Wout,
                                             const float* __restrict__ bout,
                                             float* __restrict__ out) {
    __shared__ float sMT[H * SA_STRIDE];
    __shared__ float sWo[H * H];
    __shared__ float sB[H];
    int t = threadIdx.x;
    int node0 = blockIdx.x * 64;

    for (int i = t; i < 64 * 16; i += 256) {
        int nd = i >> 4, kg = i & 15;
        float4 mm = make_float4(0.f, 0.f, 0.f, 0.f);
        if (node0 + nd < NN) mm = ((const float4*)g_m)[(node0 + nd) * 16 + kg];
        sMT[(kg * 4 + 0) * SA_STRIDE + nd] = mm.x;
        sMT[(kg * 4 + 1) * SA_STRIDE + nd] = mm.y;
        sMT[(kg * 4 + 2) * SA_STRIDE + nd] = mm.z;
        sMT[(kg * 4 + 3) * SA_STRIDE + nd] = mm.w;
    }

    #pragma unroll
    for (int i = 0; i < 4; i++)
        ((float4*)sWo)[t + 256 * i] = ((const float4*)Wout)[t + 256 * i];
    if (t < H) sB[t] = bout[t];
    __syncthreads();

    int rg = t >> 4, cg = t & 15;
    float4 b = ((float4*)sB)[cg];
    float4 acc[4];
    #pragma unroll
    for (int j = 0; j < 4; j++) acc[j] = b;

    #pragma unroll 16
    for (int k = 0; k < H; k++) {
        float4 av = *(const float4*)&sMT[k * SA_STRIDE + rg * 4];
        float4 w  = ((const float4*)sWo)[k * 16 + cg];
        acc[0].x += av.x * w.x; acc[0].y += av.x * w.y; acc[0].z += av.x * w.z; acc[0].w += av.x * w.w;
        acc[1].x += av.y * w.x; acc[1].y += av.y * w.y; acc[1].z += av.y * w.z; acc[1].w += av.y * w.w;
        acc[2].x += av.z * w.x; acc[2].y += av.z * w.y; acc[2].z += av.z * w.z; acc[2].w += av.z * w.w;
        acc[3].x += av.w * w.x; acc[3].y += av.w * w.y; acc[3].z += av.w * w.z; acc[3].w += av.w * w.w;
    }

    int nbase = node0 + rg * 4;
    #pragma unroll
    for (int j = 0; j < 4; j++) {
        int n = nbase + j;
        if (n < NN) ((float4*)out)[n * 16 + cg] = acc[j];
    }
}

extern "C" void kernel_launch(void* const* d_in, const int* in_sizes, int n_in,
                              void* d_out, int out_size) {
    const float* risk = (const float*)d_in[0];
    // d_in[1] = edge_weight (unused by the reference)
    const float* Win  = (const float*)d_in[2];
    const float* bin  = (const float*)d_in[3];
    const float* Wrel = (const float*)d_in[4];
    const float* Wout = (const float*)d_in[5];
    const float* bout = (const float*)d_in[6];
    const int*   ei   = (const int*)d_in[7];   // [2, NE]: row (dst), col (src)
    const int*   et   = (const int*)d_in[8];
    float* out = (float*)d_out;

    cudaFuncSetAttribute(k_node_tc, cudaFuncAttributeMaxDynamicSharedMemorySize, TCN_SMEM);

    k_zero<<<128, 256>>>();
    k_wcomb<<<(6 * H * H + 255) / 256, 256>>>(Win, bin, Wrel);
    k_deg<<<(NE + 255) / 256, 256>>>(ei);
    k_bsum<<<NB, 256>>>();
    k_scanb<<<1, 256>>>();
    k_off<<<NB, 256>>>();
    k_scatter<<<(NE + 255) / 256, 256>>>(ei, et);
    k_node_tc<<<(NN + 127) / 128, 256, TCN_SMEM>>>(risk);
    k_edge2<<<(NN + 7) / 8, 256>>>();
    k_out<<<(NN + 63) / 64, 256>>>(Wout, bout, out);
}